// round 14
// baseline (speedup 1.0000x reference)
#include <cuda_runtime.h>
#include <cuda_fp16.h>
#include <math.h>
#include <stdint.h>

#define SEQ    2048
#define HDIM   1024
#define NH     16
#define HS     64
#define MTOT   4096            // B*S
#define N_QKV  3072            // 3*HDIM

// Scratch (allocation-free rule: device globals)
__device__ __half   g_xh   [(size_t)MTOT * HDIM];        // half(x)
__device__ __half   g_xph  [(size_t)MTOT * HDIM];        // half(x+pos)
__device__ __half   g_aoh  [(size_t)MTOT * HDIM];        // attention out, half
__device__ __half   g_qkh  [(size_t)MTOT * 2048];        // q|k half row-major
__device__ __half   g_vT   [(size_t)HDIM * MTOT];        // v transposed
__device__ uint32_t g_wqkvT2[(size_t)N_QKV * (HDIM / 2)]; // W_qkv^T half2
__device__ uint32_t g_woutT2[(size_t)HDIM * (HDIM / 2)];  // W_out^T half2

// ---------------------------------------------------------------------------
// helpers
// ---------------------------------------------------------------------------
__device__ __forceinline__ uint32_t f22h2(float x, float y) {
    __half2 h = __floats2half2_rn(x, y);
    return *(uint32_t*)&h;
}
__device__ __forceinline__ float ex2(float x) {
    float r;
    asm("ex2.approx.ftz.f32 %0, %1;" : "=f"(r) : "f"(x));
    return r;
}
__device__ __forceinline__ uint32_t smem_u32(const void* p) {
    uint32_t a;
    asm("{ .reg .u64 t; cvta.to.shared.u64 t, %1; cvt.u32.u64 %0, t; }"
        : "=r"(a) : "l"(p));
    return a;
}

#define MMA16(d, a, b)                                                         \
    asm volatile(                                                              \
        "mma.sync.aligned.m16n8k16.row.col.f32.f16.f16.f32 "                   \
        "{%0,%1,%2,%3},{%4,%5,%6,%7},{%8,%9},{%0,%1,%2,%3};"                   \
        : "+f"((d)[0]), "+f"((d)[1]), "+f"((d)[2]), "+f"((d)[3])               \
        : "r"((a)[0]), "r"((a)[1]), "r"((a)[2]), "r"((a)[3]),                  \
          "r"((b)[0]), "r"((b)[1]))

#define LDSM4(r0, r1, r2, r3, addr)                                            \
    asm volatile("ldmatrix.sync.aligned.m8n8.x4.shared.b16 {%0,%1,%2,%3}, [%4];" \
        : "=r"(r0), "=r"(r1), "=r"(r2), "=r"(r3) : "r"(addr))

#define CP16(dst_u32, src_ptr)                                                 \
    asm volatile("cp.async.cg.shared.global [%0], [%1], 16;"                   \
        :: "r"(dst_u32), "l"(src_ptr))
#define CP_COMMIT() asm volatile("cp.async.commit_group;" ::: "memory")
#define CP_WAIT(n)  asm volatile("cp.async.wait_group %0;" :: "n"(n) : "memory")

// ---------------------------------------------------------------------------
// merged prep: block < 4096           -> xh/xph row conversion
//              4096 <= block < 7168   -> W_qkv transpose tile
//              7168 <= block < 8192   -> W_out transpose tile
// ---------------------------------------------------------------------------
__global__ __launch_bounds__(256)
void prep_all(const float* __restrict__ x, const float* __restrict__ pos,
              const float* __restrict__ Wqkv, const float* __restrict__ Wout,
              __half* __restrict__ xh, __half* __restrict__ xph,
              uint32_t* __restrict__ wqkvT2, uint32_t* __restrict__ woutT2)
{
    const int bid = blockIdx.x;
    const int tid = threadIdx.x;

    if (bid < MTOT) {
        const int m = bid;
        const int c = tid * 4;
        float4 xv = *(const float4*)(x + (size_t)m * HDIM + c);
        float4 pv = *(const float4*)(pos + (size_t)(m & (SEQ - 1)) * HDIM + c);
        uint2 u0; u0.x = f22h2(xv.x, xv.y); u0.y = f22h2(xv.z, xv.w);
        *(uint2*)(xh + (size_t)m * HDIM + c) = u0;
        uint2 u1; u1.x = f22h2(xv.x + pv.x, xv.y + pv.y);
        u1.y = f22h2(xv.z + pv.z, xv.w + pv.w);
        *(uint2*)(xph + (size_t)m * HDIM + c) = u1;
        return;
    }

    __shared__ float tile[32][33];
    const float* W;
    uint32_t* WT2;
    int bx, by, N;
    if (bid < MTOT + 3072) {
        int id = bid - MTOT;
        W = Wqkv; WT2 = wqkvT2; N = N_QKV;
        bx = id % (N_QKV / 32);
        by = id / (N_QKV / 32);
    } else {
        int id = bid - MTOT - 3072;
        W = Wout; WT2 = woutT2; N = HDIM;
        bx = id % (HDIM / 32);
        by = id / (HDIM / 32);
    }
    const int K = HDIM;
    const int tx = tid & 31;
    const int ty = tid >> 5;
    #pragma unroll
    for (int i = ty; i < 32; i += 8)
        tile[i][tx] = W[(size_t)(by * 32 + i) * N + bx * 32 + tx];
    __syncthreads();
    #pragma unroll
    for (int it = 0; it < 2; it++) {
        int id = tid + it * 256;
        int nl = id >> 4;
        int kh = id & 15;
        WT2[(size_t)(bx * 32 + nl) * (K / 2) + by * 16 + kh] =
            f22h2(tile[2 * kh][nl], tile[2 * kh + 1][nl]);
    }
}

// ---------------------------------------------------------------------------
// fp16 GEMM (R12-exact): CTA tile 128x256, 512 thr, warp tile 32x64,
// K-step 64, 2-stage double buffer, ONE barrier per 64-k iteration.
// ---------------------------------------------------------------------------
#define GEMM_A_WORDS 4608
#define GEMM_B_WORDS 9216
#define GEMM_STG     (GEMM_A_WORDS + GEMM_B_WORDS)
#define GEMM_SMEM    (2 * GEMM_STG * 4)

__global__ __launch_bounds__(512, 1)
void gemm_h16(const __half* __restrict__ A0, const __half* __restrict__ A1,
              const uint32_t* __restrict__ BT2, float* __restrict__ Cf,
              __half* __restrict__ qkh, __half* __restrict__ vT,
              int N, int K, int ncut, int outmode)
{
    extern __shared__ uint32_t gsm[];
    const uint32_t s_u = smem_u32(gsm);

    const int tid  = threadIdx.x;
    const int lane = tid & 31;
    const int warp = tid >> 5;
    const int wm   = warp >> 2;
    const int wn   = warp & 3;
    const int g    = lane >> 2;
    const int t    = lane & 3;

    const int m0 = blockIdx.y * 128;
    const int n0 = blockIdx.x * 256;
    const __half* Aptr = (n0 < ncut) ? A0 : A1;

    const int lrow = lane & 15;
    const int lckA = lane >> 4;
    const int lnB  = (lane & 7) + 8 * ((lane >> 4) & 1);
    const int lckB = (lane >> 3) & 1;

    auto stage = [&](int tt, int bf) {
        const int k0 = tt << 6;
        const uint32_t abase = s_u + (uint32_t)(bf * GEMM_STG) * 4;
        const uint32_t bbase = abase + GEMM_A_WORDS * 4;
        #pragma unroll
        for (int it = 0; it < 2; it++) {
            int id  = tid + it * 512;
            int row = id >> 3;
            int ch  = id & 7;
            CP16(abase + (uint32_t)(row * 36 + ch * 4) * 4,
                 Aptr + (size_t)(m0 + row) * K + k0 + ch * 8);
        }
        #pragma unroll
        for (int it = 0; it < 4; it++) {
            int id = tid + it * 512;
            int n  = id >> 3;
            int ch = id & 7;
            CP16(bbase + (uint32_t)(n * 36 + ch * 4) * 4,
                 BT2 + (size_t)(n0 + n) * (K / 2) + (k0 >> 1) + ch * 4);
        }
    };

    float acc[2][8][4];
    #pragma unroll
    for (int i = 0; i < 2; i++)
        #pragma unroll
        for (int j = 0; j < 8; j++)
            #pragma unroll
            for (int c = 0; c < 4; c++)
                acc[i][j][c] = 0.0f;

    const int T = K >> 6;
    stage(0, 0); CP_COMMIT();

    for (int tt = 0; tt < T; tt++) {
        const int bf = tt & 1;
        CP_WAIT(0);
        __syncthreads();
        if (tt + 1 < T) {
            stage(tt + 1, bf ^ 1);
            CP_COMMIT();
        }

        const uint32_t ab = s_u + (uint32_t)(bf * GEMM_STG) * 4;
        const uint32_t bb = ab + GEMM_A_WORDS * 4;
        #pragma unroll
        for (int ks = 0; ks < 4; ks++) {
            uint32_t afr[2][4], bfr[8][2];
            #pragma unroll
            for (int mi = 0; mi < 2; mi++) {
                int row = wm * 32 + mi * 16 + lrow;
                LDSM4(afr[mi][0], afr[mi][1], afr[mi][2], afr[mi][3],
                      ab + (uint32_t)(row * 36 + (2 * ks + lckA) * 4) * 4);
            }
            #pragma unroll
            for (int p = 0; p < 4; p++) {
                int n = wn * 64 + p * 16 + lnB;
                LDSM4(bfr[2 * p][0], bfr[2 * p][1],
                      bfr[2 * p + 1][0], bfr[2 * p + 1][1],
                      bb + (uint32_t)(n * 36 + (2 * ks + lckB) * 4) * 4);
            }
            #pragma unroll
            for (int mi = 0; mi < 2; mi++)
                #pragma unroll
                for (int ni = 0; ni < 8; ni++)
                    MMA16(acc[mi][ni], afr[mi], bfr[ni]);
        }
    }

    // ---- epilogue ----
    if (outmode == 0) {
        #pragma unroll
        for (int mi = 0; mi < 2; mi++) {
            int row = m0 + wm * 32 + mi * 16 + g;
            #pragma unroll
            for (int ni = 0; ni < 8; ni++) {
                int col = n0 + wn * 64 + ni * 8 + 2 * t;
                *(float2*)(Cf + (size_t)row * N + col) =
                    make_float2(acc[mi][ni][0], acc[mi][ni][1]);
                *(float2*)(Cf + (size_t)(row + 8) * N + col) =
                    make_float2(acc[mi][ni][2], acc[mi][ni][3]);
            }
        }
    } else if (n0 < 2048) {
        #pragma unroll
        for (int mi = 0; mi < 2; mi++) {
            int row = m0 + wm * 32 + mi * 16 + g;
            #pragma unroll
            for (int ni = 0; ni < 8; ni++) {
                int col = n0 + wn * 64 + ni * 8 + 2 * t;
                *(uint32_t*)(qkh + (size_t)row * 2048 + col) =
                    f22h2(acc[mi][ni][0], acc[mi][ni][1]);
                *(uint32_t*)(qkh + (size_t)(row + 8) * 2048 + col) =
                    f22h2(acc[mi][ni][2], acc[mi][ni][3]);
            }
        }
    } else {
        #pragma unroll
        for (int mi = 0; mi < 2; mi++) {
            int row = m0 + wm * 32 + mi * 16 + g;
            #pragma unroll
            for (int ni = 0; ni < 8; ni++) {
                int colv = n0 - 2048 + wn * 64 + ni * 8 + 2 * t;
                vT[(size_t)colv * MTOT + row]           = __float2half_rn(acc[mi][ni][0]);
                vT[(size_t)(colv + 1) * MTOT + row]     = __float2half_rn(acc[mi][ni][1]);
                vT[(size_t)colv * MTOT + row + 8]       = __float2half_rn(acc[mi][ni][2]);
                vT[(size_t)(colv + 1) * MTOT + row + 8] = __float2half_rn(acc[mi][ni][3]);
            }
        }
    }
}

// ---------------------------------------------------------------------------
// Flash attention (causal): MMA-dispatch-bound regime -> remove MMAs.
// - row sums via fp32 FADD (FMA pipe) instead of ones-column MMA (-6% MMAs)
// - diagonal-tile skipping: warp w skips key groups p>w (QK) and kk>w (PV)
//   on kt==qt (exact; masked groups / P==0 groups)            (-5% MMAs)
// Early staging, double-buffered cp.async, Q/P in regs, 1 sync/tile.
// ---------------------------------------------------------------------------
#define ATTN_SMEM_BYTES (4 * 4096 * 4)

__global__ __launch_bounds__(256, 2)
void attn_h16(const __half* __restrict__ qkh, const __half* __restrict__ vT,
              __half* __restrict__ aoh)
{
    extern __shared__ uint32_t usm[];
    const uint32_t usm_u = smem_u32(usm);

    const int tid  = threadIdx.x;
    const int lane = tid & 31;
    const int warp = tid >> 5;
    const int g    = lane >> 2;
    const int t    = lane & 3;
    const int q0   = warp * 16;
    const unsigned FULL = 0xffffffffu;

    const int lnB  = (lane & 7) + 8 * ((lane >> 4) & 1);
    const int lckB = (lane >> 3) & 1;

    const int bh = blockIdx.y;
    const int b  = bh >> 4;
    const int h  = bh & 15;
    const int qt = (int)gridDim.x - 1 - (int)blockIdx.x;

    // ---- Q fragments in registers (scaled by exact 0.125) ----
    uint32_t qf[4][4];
    {
        const __half* qb = qkh + (size_t)(b * SEQ + qt * 128 + q0 + g) * 2048 + h * HS;
        const __half2 s = __floats2half2_rn(0.125f, 0.125f);
        #pragma unroll
        for (int ks = 0; ks < 4; ks++) {
            __half2 v0 = *(const __half2*)(qb + ks * 16 + 2 * t);
            __half2 v1 = *(const __half2*)(qb + 8 * 2048 + ks * 16 + 2 * t);
            __half2 v2 = *(const __half2*)(qb + ks * 16 + 2 * t + 8);
            __half2 v3 = *(const __half2*)(qb + 8 * 2048 + ks * 16 + 2 * t + 8);
            v0 = __hmul2(v0, s); v1 = __hmul2(v1, s);
            v2 = __hmul2(v2, s); v3 = __hmul2(v3, s);
            qf[ks][0] = *(uint32_t*)&v0; qf[ks][1] = *(uint32_t*)&v1;
            qf[ks][2] = *(uint32_t*)&v2; qf[ks][3] = *(uint32_t*)&v3;
        }
    }

    const __half* kb0 = qkh + (size_t)(b * SEQ) * 2048 + 1024 + h * HS;
    const __half* vb0 = vT + (size_t)(h * HS) * MTOT + b * SEQ;

    auto stageKV = [&](int kt2, int bf) {
        const uint32_t kbase = usm_u + (uint32_t)(bf * 8192) * 4;
        const __half* kb = kb0 + (size_t)(kt2 * 128) * 2048;
        #pragma unroll
        for (int it = 0; it < 4; it++) {
            int id  = tid + it * 256;
            int key = id >> 3;
            int ch  = id & 7;
            CP16(kbase + (uint32_t)(((key << 5) + ((ch ^ (key & 7)) << 2)) << 2),
                 kb + (size_t)key * 2048 + ch * 8);
        }
        const __half* vb = vb0 + kt2 * 128;
        #pragma unroll
        for (int it = 0; it < 4; it++) {
            int id = tid + it * 256;
            int d  = id >> 4;
            int ch = id & 15;
            CP16(kbase + 4096 * 4 +
                     (uint32_t)((d * 64 + ((ch ^ (d & 7)) << 2)) << 2),
                 vb + (size_t)d * MTOT + ch * 8);
        }
    };

    float m0r = -1e30f, m1r = -1e30f, l0r = 0.0f, l1r = 0.0f;
    float o[8][4];
    #pragma unroll
    for (int ni = 0; ni < 8; ni++)
        o[ni][0] = o[ni][1] = o[ni][2] = o[ni][3] = 0.0f;

    const float L2E = 1.4426950408889634f;

    stageKV(0, 0); CP_COMMIT();
    CP_WAIT(0);
    __syncthreads();

    int buf = 0;
    for (int kt = 0; kt <= qt; kt++) {
        const uint32_t kb_u = usm_u + (uint32_t)(buf * 8192) * 4;
        const uint32_t vb_u = kb_u + 4096 * 4;
        const bool diag = (kt == qt);

        // ---- S = Q @ K^T (diag: skip fully-masked key groups p > warp) ----
        float sacc[16][4];
        #pragma unroll
        for (int ni = 0; ni < 16; ni++)
            sacc[ni][0] = sacc[ni][1] = sacc[ni][2] = sacc[ni][3] = 0.0f;

        #pragma unroll
        for (int ks = 0; ks < 4; ks++) {
            #pragma unroll
            for (int p = 0; p < 8; p++) {
                if (!diag || p <= warp) {
                    int key = p * 16 + lnB;
                    int ck  = 2 * ks + lckB;
                    uint32_t addr = kb_u +
                        (uint32_t)(((key << 5) + ((ck ^ (key & 7)) << 2)) << 2);
                    uint32_t b0, b1, b2, b3;
                    LDSM4(b0, b1, b2, b3, addr);
                    uint32_t f0[2] = { b0, b1 };
                    uint32_t f1[2] = { b2, b3 };
                    MMA16(sacc[2 * p],     qf[ks], f0);
                    MMA16(sacc[2 * p + 1], qf[ks], f1);
                }
            }
        }

        // ---- causal mask (diag; also masks skipped groups, sacc=0 there) ----
        const int r0l = q0 + g, r1l = r0l + 8;
        if (diag) {
            #pragma unroll
            for (int ni = 0; ni < 16; ni++) {
                int c = ni * 8 + 2 * t;
                if (c     > r0l) sacc[ni][0] = -1e30f;
                if (c + 1 > r0l) sacc[ni][1] = -1e30f;
                if (c     > r1l) sacc[ni][2] = -1e30f;
                if (c + 1 > r1l) sacc[ni][3] = -1e30f;
            }
        }

        // ---- stage next K/V tile EARLY (QK reads of this buffer done) ----
        if (kt < qt) {
            stageKV(kt + 1, buf ^ 1);
            CP_COMMIT();
        }

        // ---- row max (quad reduce) ----
        float rm0 = -1e30f, rm1 = -1e30f;
        #pragma unroll
        for (int ni = 0; ni < 16; ni++) {
            rm0 = fmaxf(rm0, fmaxf(sacc[ni][0], sacc[ni][1]));
            rm1 = fmaxf(rm1, fmaxf(sacc[ni][2], sacc[ni][3]));
        }
        rm0 = fmaxf(rm0, __shfl_xor_sync(FULL, rm0, 1));
        rm0 = fmaxf(rm0, __shfl_xor_sync(FULL, rm0, 2));
        rm1 = fmaxf(rm1, __shfl_xor_sync(FULL, rm1, 1));
        rm1 = fmaxf(rm1, __shfl_xor_sync(FULL, rm1, 2));

        float nm0 = fmaxf(m0r, rm0), nm1 = fmaxf(m1r, rm1);
        float fac0 = ex2((m0r - nm0) * L2E), fac1 = ex2((m1r - nm1) * L2E);
        float nb0 = nm0 * L2E, nb1 = nm1 * L2E;

        // ---- exp (fp32 MUFU) + fp32 row sums (FMA pipe) + pack P ----
        uint32_t p01[16], p23[16];
        float rs0 = 0.0f, rs1 = 0.0f;
        #pragma unroll
        for (int ni = 0; ni < 16; ni++) {
            float e00 = ex2(fmaf(sacc[ni][0], L2E, -nb0));
            float e01 = ex2(fmaf(sacc[ni][1], L2E, -nb0));
            float e10 = ex2(fmaf(sacc[ni][2], L2E, -nb1));
            float e11 = ex2(fmaf(sacc[ni][3], L2E, -nb1));
            rs0 += e00 + e01;
            rs1 += e10 + e11;
            p01[ni] = f22h2(e00, e01);
            p23[ni] = f22h2(e10, e11);
        }
        rs0 += __shfl_xor_sync(FULL, rs0, 1);
        rs0 += __shfl_xor_sync(FULL, rs0, 2);
        rs1 += __shfl_xor_sync(FULL, rs1, 1);
        rs1 += __shfl_xor_sync(FULL, rs1, 2);

        l0r = l0r * fac0 + rs0;
        l1r = l1r * fac1 + rs1;
        m0r = nm0; m1r = nm1;
        #pragma unroll
        for (int ni = 0; ni < 8; ni++) {
            o[ni][0] *= fac0; o[ni][1] *= fac0;
            o[ni][2] *= fac1; o[ni][3] *= fac1;
        }

        // ---- O += P @ V (diag: skip P==0 key groups kk > warp) ----
        #pragma unroll
        for (int kk = 0; kk < 8; kk++) {
            if (!diag || kk <= warp) {
                uint32_t afr[4] = { p01[2 * kk], p23[2 * kk],
                                    p01[2 * kk + 1], p23[2 * kk + 1] };
                #pragma unroll
                for (int p = 0; p < 4; p++) {
                    int d  = p * 16 + lnB;
                    int ck = 2 * kk + lckB;
                    uint32_t addr = vb_u +
                        (uint32_t)(((d << 6) + ((ck ^ (d & 7)) << 2)) << 2);
                    uint32_t b0, b1, b2, b3;
                    LDSM4(b0, b1, b2, b3, addr);
                    uint32_t f0[2] = { b0, b1 };
                    uint32_t f1[2] = { b2, b3 };
                    MMA16(o[2 * p],     afr, f0);
                    MMA16(o[2 * p + 1], afr, f1);
                }
            }
        }

        if (kt < qt) {
            CP_WAIT(0);
            __syncthreads();
            buf ^= 1;
        }
    }

    // ---- normalize + write half ao ----
    float inv0 = 1.0f / l0r, inv1 = 1.0f / l1r;
    __half* aobase = aoh + (size_t)(b * SEQ + qt * 128) * HDIM + h * HS;
    #pragma unroll
    for (int ni = 0; ni < 8; ni++) {
        int c = ni * 8 + 2 * t;
        *(uint32_t*)(aobase + (size_t)(q0 + g) * HDIM + c) =
            f22h2(o[ni][0] * inv0, o[ni][1] * inv0);
        *(uint32_t*)(aobase + (size_t)(q0 + g + 8) * HDIM + c) =
            f22h2(o[ni][2] * inv1, o[ni][3] * inv1);
    }
}

// ---------------------------------------------------------------------------
extern "C" void kernel_launch(void* const* d_in, const int* in_sizes, int n_in,
                              void* d_out, int out_size)
{
    const float* x    = (const float*)d_in[0];
    const float* pos  = (const float*)d_in[1];
    const float* Wqkv = (const float*)d_in[2];
    const float* Wout = (const float*)d_in[3];
    float* out = (float*)d_out;

    __half *xh_p, *xph_p, *aoh_p, *qkh_p, *vT_p;
    uint32_t *wqkvT2_p, *woutT2_p;
    cudaGetSymbolAddress((void**)&xh_p,     g_xh);
    cudaGetSymbolAddress((void**)&xph_p,    g_xph);
    cudaGetSymbolAddress((void**)&aoh_p,    g_aoh);
    cudaGetSymbolAddress((void**)&qkh_p,    g_qkh);
    cudaGetSymbolAddress((void**)&vT_p,     g_vT);
    cudaGetSymbolAddress((void**)&wqkvT2_p, g_wqkvT2);
    cudaGetSymbolAddress((void**)&woutT2_p, g_woutT2);

    // 0) merged prep: x conversion + both weight transposes in ONE launch
    prep_all<<<MTOT + 3072 + 1024, 256>>>(x, pos, Wqkv, Wout,
                                          xh_p, xph_p, wqkvT2_p, woutT2_p);

    // 1) qkv projection (128x256 CTA tile)
    {
        cudaFuncSetAttribute(gemm_h16,
                             cudaFuncAttributeMaxDynamicSharedMemorySize, GEMM_SMEM);
        dim3 grid(N_QKV / 256, MTOT / 128);
        gemm_h16<<<grid, 512, GEMM_SMEM>>>(xph_p, xh_p, wqkvT2_p, nullptr,
                                           qkh_p, vT_p, N_QKV, HDIM, 2048, 1);
    }

    // 2) flash attention (MMA-reduced: FADD row-sums + diagonal skipping)
    {
        cudaFuncSetAttribute(attn_h16,
                             cudaFuncAttributeMaxDynamicSharedMemorySize, ATTN_SMEM_BYTES);
        dim3 grid(SEQ / 128, 2 * NH);
        attn_h16<<<grid, 256, ATTN_SMEM_BYTES>>>(qkh_p, vT_p, aoh_p);
    }

    // 3) out = ao @ Wout (fp32 output)
    {
        dim3 grid(HDIM / 256, MTOT / 128);
        gemm_h16<<<grid, 512, GEMM_SMEM>>>(aoh_p, aoh_p, woutT2_p, out,
                                           nullptr, nullptr, HDIM, HDIM, 0, 0);
    }
}

// round 15
// speedup vs baseline: 1.0721x; 1.0721x over previous
#include <cuda_runtime.h>
#include <cuda_fp16.h>
#include <math.h>
#include <stdint.h>

#define SEQ    2048
#define HDIM   1024
#define NH     16
#define HS     64
#define MTOT   4096            // B*S
#define N_QKV  3072            // 3*HDIM

// Scratch (allocation-free rule: device globals)
__device__ __half   g_xh   [(size_t)MTOT * HDIM];        // half(x)
__device__ __half   g_xph  [(size_t)MTOT * HDIM];        // half(x+pos)
__device__ __half   g_aoh  [(size_t)MTOT * HDIM];        // attention out, half
__device__ __half   g_qkh  [(size_t)MTOT * 2048];        // q|k half row-major
__device__ __half   g_vT   [(size_t)HDIM * MTOT];        // v transposed
__device__ uint32_t g_wqkvT2[(size_t)N_QKV * (HDIM / 2)]; // W_qkv^T half2
__device__ uint32_t g_woutT2[(size_t)HDIM * (HDIM / 2)];  // W_out^T half2

// ---------------------------------------------------------------------------
// helpers
// ---------------------------------------------------------------------------
__device__ __forceinline__ uint32_t f22h2(float x, float y) {
    __half2 h = __floats2half2_rn(x, y);
    return *(uint32_t*)&h;
}
__device__ __forceinline__ float ex2(float x) {
    float r;
    asm("ex2.approx.ftz.f32 %0, %1;" : "=f"(r) : "f"(x));
    return r;
}
__device__ __forceinline__ uint32_t ex2h2(float a, float b) {
    uint32_t arg = f22h2(a, b), r;
    asm("ex2.approx.f16x2 %0, %1;" : "=r"(r) : "r"(arg));
    return r;
}
__device__ __forceinline__ uint32_t smem_u32(const void* p) {
    uint32_t a;
    asm("{ .reg .u64 t; cvta.to.shared.u64 t, %1; cvt.u32.u64 %0, t; }"
        : "=r"(a) : "l"(p));
    return a;
}

#define MMA16(d, a, b)                                                         \
    asm volatile(                                                              \
        "mma.sync.aligned.m16n8k16.row.col.f32.f16.f16.f32 "                   \
        "{%0,%1,%2,%3},{%4,%5,%6,%7},{%8,%9},{%0,%1,%2,%3};"                   \
        : "+f"((d)[0]), "+f"((d)[1]), "+f"((d)[2]), "+f"((d)[3])               \
        : "r"((a)[0]), "r"((a)[1]), "r"((a)[2]), "r"((a)[3]),                  \
          "r"((b)[0]), "r"((b)[1]))

#define LDSM4(r0, r1, r2, r3, addr)                                            \
    asm volatile("ldmatrix.sync.aligned.m8n8.x4.shared.b16 {%0,%1,%2,%3}, [%4];" \
        : "=r"(r0), "=r"(r1), "=r"(r2), "=r"(r3) : "r"(addr))

#define CP16(dst_u32, src_ptr)                                                 \
    asm volatile("cp.async.cg.shared.global [%0], [%1], 16;"                   \
        :: "r"(dst_u32), "l"(src_ptr))
#define CP_COMMIT() asm volatile("cp.async.commit_group;" ::: "memory")
#define CP_WAIT(n)  asm volatile("cp.async.wait_group %0;" :: "n"(n) : "memory")

// ---------------------------------------------------------------------------
// merged prep (R13-exact)
// ---------------------------------------------------------------------------
__global__ __launch_bounds__(256)
void prep_all(const float* __restrict__ x, const float* __restrict__ pos,
              const float* __restrict__ Wqkv, const float* __restrict__ Wout,
              __half* __restrict__ xh, __half* __restrict__ xph,
              uint32_t* __restrict__ wqkvT2, uint32_t* __restrict__ woutT2)
{
    const int bid = blockIdx.x;
    const int tid = threadIdx.x;

    if (bid < MTOT) {
        const int m = bid;
        const int c = tid * 4;
        float4 xv = *(const float4*)(x + (size_t)m * HDIM + c);
        float4 pv = *(const float4*)(pos + (size_t)(m & (SEQ - 1)) * HDIM + c);
        uint2 u0; u0.x = f22h2(xv.x, xv.y); u0.y = f22h2(xv.z, xv.w);
        *(uint2*)(xh + (size_t)m * HDIM + c) = u0;
        uint2 u1; u1.x = f22h2(xv.x + pv.x, xv.y + pv.y);
        u1.y = f22h2(xv.z + pv.z, xv.w + pv.w);
        *(uint2*)(xph + (size_t)m * HDIM + c) = u1;
        return;
    }

    __shared__ float tile[32][33];
    const float* W;
    uint32_t* WT2;
    int bx, by, N;
    if (bid < MTOT + 3072) {
        int id = bid - MTOT;
        W = Wqkv; WT2 = wqkvT2; N = N_QKV;
        bx = id % (N_QKV / 32);
        by = id / (N_QKV / 32);
    } else {
        int id = bid - MTOT - 3072;
        W = Wout; WT2 = woutT2; N = HDIM;
        bx = id % (HDIM / 32);
        by = id / (HDIM / 32);
    }
    const int K = HDIM;
    const int tx = tid & 31;
    const int ty = tid >> 5;
    #pragma unroll
    for (int i = ty; i < 32; i += 8)
        tile[i][tx] = W[(size_t)(by * 32 + i) * N + bx * 32 + tx];
    __syncthreads();
    #pragma unroll
    for (int it = 0; it < 2; it++) {
        int id = tid + it * 256;
        int nl = id >> 4;
        int kh = id & 15;
        WT2[(size_t)(bx * 32 + nl) * (K / 2) + by * 16 + kh] =
            f22h2(tile[2 * kh][nl], tile[2 * kh + 1][nl]);
    }
}

// ---------------------------------------------------------------------------
// fp16 GEMM, templated on NFR (n-fragments per warp):
//   NFR=8 -> CTA tile 128x256, 1 CTA/SM  (gemm1: grid 384)
//   NFR=4 -> CTA tile 128x128, 2 CTA/SM  (gemm2: grid 256, full-chip 1 wave)
// 512 thr, warp tile 32 x (8*NFR), K-step 64, 2-stage double buffer,
// ONE barrier per 64-k iteration. Rows at 36-word stride (conflict-free).
// ---------------------------------------------------------------------------
#define GEMM_A_WORDS 4608            // 128 rows x 36 words
template<int NFR>
struct GemmCfg {
    static constexpr int NTILE   = 32 * NFR;           // CTA n-tile
    static constexpr int B_WORDS = NTILE * 36;
    static constexpr int STG     = GEMM_A_WORDS + B_WORDS;
    static constexpr int SMEM    = 2 * STG * 4;
};

template<int NFR>
__global__ __launch_bounds__(512, (NFR == 4) ? 2 : 1)
void gemm_h16(const __half* __restrict__ A0, const __half* __restrict__ A1,
              const uint32_t* __restrict__ BT2, float* __restrict__ Cf,
              __half* __restrict__ qkh, __half* __restrict__ vT,
              int N, int K, int ncut, int outmode)
{
    using C = GemmCfg<NFR>;
    extern __shared__ uint32_t gsm[];
    const uint32_t s_u = smem_u32(gsm);

    const int tid  = threadIdx.x;
    const int lane = tid & 31;
    const int warp = tid >> 5;
    const int wm   = warp >> 2;
    const int wn   = warp & 3;
    const int g    = lane >> 2;
    const int t    = lane & 3;

    const int m0 = blockIdx.y * 128;
    const int n0 = blockIdx.x * C::NTILE;
    const __half* Aptr = (n0 < ncut) ? A0 : A1;

    const int lrow = lane & 15;
    const int lckA = lane >> 4;
    const int lnB  = (lane & 7) + 8 * ((lane >> 4) & 1);
    const int lckB = (lane >> 3) & 1;

    auto stage = [&](int tt, int bf) {
        const int k0 = tt << 6;
        const uint32_t abase = s_u + (uint32_t)(bf * C::STG) * 4;
        const uint32_t bbase = abase + GEMM_A_WORDS * 4;
        #pragma unroll
        for (int it = 0; it < 2; it++) {
            int id  = tid + it * 512;
            int row = id >> 3;
            int ch  = id & 7;
            CP16(abase + (uint32_t)(row * 36 + ch * 4) * 4,
                 Aptr + (size_t)(m0 + row) * K + k0 + ch * 8);
        }
        #pragma unroll
        for (int it = 0; it < NFR / 2; it++) {
            int id = tid + it * 512;
            int n  = id >> 3;
            int ch = id & 7;
            CP16(bbase + (uint32_t)(n * 36 + ch * 4) * 4,
                 BT2 + (size_t)(n0 + n) * (K / 2) + (k0 >> 1) + ch * 4);
        }
    };

    float acc[2][NFR][4];
    #pragma unroll
    for (int i = 0; i < 2; i++)
        #pragma unroll
        for (int j = 0; j < NFR; j++)
            #pragma unroll
            for (int c = 0; c < 4; c++)
                acc[i][j][c] = 0.0f;

    const int T = K >> 6;
    stage(0, 0); CP_COMMIT();

    for (int tt = 0; tt < T; tt++) {
        const int bf = tt & 1;
        CP_WAIT(0);
        __syncthreads();
        if (tt + 1 < T) {
            stage(tt + 1, bf ^ 1);
            CP_COMMIT();
        }

        const uint32_t ab = s_u + (uint32_t)(bf * C::STG) * 4;
        const uint32_t bb = ab + GEMM_A_WORDS * 4;
        #pragma unroll
        for (int ks = 0; ks < 4; ks++) {
            uint32_t afr[2][4], bfr[NFR][2];
            #pragma unroll
            for (int mi = 0; mi < 2; mi++) {
                int row = wm * 32 + mi * 16 + lrow;
                LDSM4(afr[mi][0], afr[mi][1], afr[mi][2], afr[mi][3],
                      ab + (uint32_t)(row * 36 + (2 * ks + lckA) * 4) * 4);
            }
            #pragma unroll
            for (int p = 0; p < NFR / 2; p++) {
                int n = wn * (8 * NFR) + p * 16 + lnB;
                LDSM4(bfr[2 * p][0], bfr[2 * p][1],
                      bfr[2 * p + 1][0], bfr[2 * p + 1][1],
                      bb + (uint32_t)(n * 36 + (2 * ks + lckB) * 4) * 4);
            }
            #pragma unroll
            for (int mi = 0; mi < 2; mi++)
                #pragma unroll
                for (int ni = 0; ni < NFR; ni++)
                    MMA16(acc[mi][ni], afr[mi], bfr[ni]);
        }
    }

    // ---- epilogue ----
    if (outmode == 0) {
        #pragma unroll
        for (int mi = 0; mi < 2; mi++) {
            int row = m0 + wm * 32 + mi * 16 + g;
            #pragma unroll
            for (int ni = 0; ni < NFR; ni++) {
                int col = n0 + wn * (8 * NFR) + ni * 8 + 2 * t;
                *(float2*)(Cf + (size_t)row * N + col) =
                    make_float2(acc[mi][ni][0], acc[mi][ni][1]);
                *(float2*)(Cf + (size_t)(row + 8) * N + col) =
                    make_float2(acc[mi][ni][2], acc[mi][ni][3]);
            }
        }
    } else if (n0 < 2048) {
        #pragma unroll
        for (int mi = 0; mi < 2; mi++) {
            int row = m0 + wm * 32 + mi * 16 + g;
            #pragma unroll
            for (int ni = 0; ni < NFR; ni++) {
                int col = n0 + wn * (8 * NFR) + ni * 8 + 2 * t;
                *(uint32_t*)(qkh + (size_t)row * 2048 + col) =
                    f22h2(acc[mi][ni][0], acc[mi][ni][1]);
                *(uint32_t*)(qkh + (size_t)(row + 8) * 2048 + col) =
                    f22h2(acc[mi][ni][2], acc[mi][ni][3]);
            }
        }
    } else {
        #pragma unroll
        for (int mi = 0; mi < 2; mi++) {
            int row = m0 + wm * 32 + mi * 16 + g;
            #pragma unroll
            for (int ni = 0; ni < NFR; ni++) {
                int colv = n0 - 2048 + wn * (8 * NFR) + ni * 8 + 2 * t;
                vT[(size_t)colv * MTOT + row]           = __float2half_rn(acc[mi][ni][0]);
                vT[(size_t)(colv + 1) * MTOT + row]     = __float2half_rn(acc[mi][ni][1]);
                vT[(size_t)colv * MTOT + row + 8]       = __float2half_rn(acc[mi][ni][2]);
                vT[(size_t)(colv + 1) * MTOT + row + 8] = __float2half_rn(acc[mi][ni][3]);
            }
        }
    }
}

// ---------------------------------------------------------------------------
// Flash attention (causal) — R13-exact (best measured): 256 thr, 8 warps,
// fp16 mma + f16x2 exp + MMA row-sums; early next-tile staging;
// double-buffered cp.async; Q/P in regs; 1 sync/tile; 2 CTAs/SM.
// ---------------------------------------------------------------------------
#define ATTN_SMEM_BYTES (4 * 4096 * 4)

__global__ __launch_bounds__(256, 2)
void attn_h16(const __half* __restrict__ qkh, const __half* __restrict__ vT,
              __half* __restrict__ aoh)
{
    extern __shared__ uint32_t usm[];
    const uint32_t usm_u = smem_u32(usm);

    const int tid  = threadIdx.x;
    const int lane = tid & 31;
    const int warp = tid >> 5;
    const int g    = lane >> 2;
    const int t    = lane & 3;
    const int q0   = warp * 16;
    const unsigned FULL = 0xffffffffu;

    const int lnB  = (lane & 7) + 8 * ((lane >> 4) & 1);
    const int lckB = (lane >> 3) & 1;

    const int bh = blockIdx.y;
    const int b  = bh >> 4;
    const int h  = bh & 15;
    const int qt = (int)gridDim.x - 1 - (int)blockIdx.x;

    uint32_t qf[4][4];
    {
        const __half* qb = qkh + (size_t)(b * SEQ + qt * 128 + q0 + g) * 2048 + h * HS;
        const __half2 s = __floats2half2_rn(0.125f, 0.125f);
        #pragma unroll
        for (int ks = 0; ks < 4; ks++) {
            __half2 v0 = *(const __half2*)(qb + ks * 16 + 2 * t);
            __half2 v1 = *(const __half2*)(qb + 8 * 2048 + ks * 16 + 2 * t);
            __half2 v2 = *(const __half2*)(qb + ks * 16 + 2 * t + 8);
            __half2 v3 = *(const __half2*)(qb + 8 * 2048 + ks * 16 + 2 * t + 8);
            v0 = __hmul2(v0, s); v1 = __hmul2(v1, s);
            v2 = __hmul2(v2, s); v3 = __hmul2(v3, s);
            qf[ks][0] = *(uint32_t*)&v0; qf[ks][1] = *(uint32_t*)&v1;
            qf[ks][2] = *(uint32_t*)&v2; qf[ks][3] = *(uint32_t*)&v3;
        }
    }

    const __half* kb0 = qkh + (size_t)(b * SEQ) * 2048 + 1024 + h * HS;
    const __half* vb0 = vT + (size_t)(h * HS) * MTOT + b * SEQ;

    auto stageKV = [&](int kt2, int bf) {
        const uint32_t kbase = usm_u + (uint32_t)(bf * 8192) * 4;
        const __half* kb = kb0 + (size_t)(kt2 * 128) * 2048;
        #pragma unroll
        for (int it = 0; it < 4; it++) {
            int id  = tid + it * 256;
            int key = id >> 3;
            int ch  = id & 7;
            CP16(kbase + (uint32_t)(((key << 5) + ((ch ^ (key & 7)) << 2)) << 2),
                 kb + (size_t)key * 2048 + ch * 8);
        }
        const __half* vb = vb0 + kt2 * 128;
        #pragma unroll
        for (int it = 0; it < 4; it++) {
            int id = tid + it * 256;
            int d  = id >> 4;
            int ch = id & 15;
            CP16(kbase + 4096 * 4 +
                     (uint32_t)((d * 64 + ((ch ^ (d & 7)) << 2)) << 2),
                 vb + (size_t)d * MTOT + ch * 8);
        }
    };

    float m0r = -1e30f, m1r = -1e30f, l0r = 0.0f, l1r = 0.0f;
    float o[8][4];
    #pragma unroll
    for (int ni = 0; ni < 8; ni++)
        o[ni][0] = o[ni][1] = o[ni][2] = o[ni][3] = 0.0f;

    const float L2E = 1.4426950408889634f;
    const uint32_t ONES2 = 0x3C003C00u;

    stageKV(0, 0); CP_COMMIT();
    CP_WAIT(0);
    __syncthreads();

    int buf = 0;
    for (int kt = 0; kt <= qt; kt++) {
        const uint32_t kb_u = usm_u + (uint32_t)(buf * 8192) * 4;
        const uint32_t vb_u = kb_u + 4096 * 4;

        // ---- S = Q @ K^T ----
        float sacc[16][4];
        #pragma unroll
        for (int ni = 0; ni < 16; ni++)
            sacc[ni][0] = sacc[ni][1] = sacc[ni][2] = sacc[ni][3] = 0.0f;

        #pragma unroll
        for (int ks = 0; ks < 4; ks++) {
            #pragma unroll
            for (int p = 0; p < 8; p++) {
                int key = p * 16 + lnB;
                int ck  = 2 * ks + lckB;
                uint32_t addr = kb_u +
                    (uint32_t)(((key << 5) + ((ck ^ (key & 7)) << 2)) << 2);
                uint32_t b0, b1, b2, b3;
                LDSM4(b0, b1, b2, b3, addr);
                uint32_t f0[2] = { b0, b1 };
                uint32_t f1[2] = { b2, b3 };
                MMA16(sacc[2 * p],     qf[ks], f0);
                MMA16(sacc[2 * p + 1], qf[ks], f1);
            }
        }

        // ---- causal mask (diagonal tile only) ----
        const int r0l = q0 + g, r1l = r0l + 8;
        if (kt == qt) {
            #pragma unroll
            for (int ni = 0; ni < 16; ni++) {
                int c = ni * 8 + 2 * t;
                if (c     > r0l) sacc[ni][0] = -1e30f;
                if (c + 1 > r0l) sacc[ni][1] = -1e30f;
                if (c     > r1l) sacc[ni][2] = -1e30f;
                if (c + 1 > r1l) sacc[ni][3] = -1e30f;
            }
        }

        // ---- stage next K/V tile EARLY ----
        if (kt < qt) {
            stageKV(kt + 1, buf ^ 1);
            CP_COMMIT();
        }

        // ---- row max (quad reduce) ----
        float rm0 = -1e30f, rm1 = -1e30f;
        #pragma unroll
        for (int ni = 0; ni < 16; ni++) {
            rm0 = fmaxf(rm0, fmaxf(sacc[ni][0], sacc[ni][1]));
            rm1 = fmaxf(rm1, fmaxf(sacc[ni][2], sacc[ni][3]));
        }
        rm0 = fmaxf(rm0, __shfl_xor_sync(FULL, rm0, 1));
        rm0 = fmaxf(rm0, __shfl_xor_sync(FULL, rm0, 2));
        rm1 = fmaxf(rm1, __shfl_xor_sync(FULL, rm1, 1));
        rm1 = fmaxf(rm1, __shfl_xor_sync(FULL, rm1, 2));

        float nm0 = fmaxf(m0r, rm0), nm1 = fmaxf(m1r, rm1);
        float fac0 = ex2((m0r - nm0) * L2E), fac1 = ex2((m1r - nm1) * L2E);
        float nb0 = nm0 * L2E, nb1 = nm1 * L2E;

        // ---- exp via f16x2 MUFU: result is the packed P fragment ----
        uint32_t p01[16], p23[16];
        #pragma unroll
        for (int ni = 0; ni < 16; ni++) {
            p01[ni] = ex2h2(fmaf(sacc[ni][0], L2E, -nb0),
                            fmaf(sacc[ni][1], L2E, -nb0));
            p23[ni] = ex2h2(fmaf(sacc[ni][2], L2E, -nb1),
                            fmaf(sacc[ni][3], L2E, -nb1));
        }

        m0r = nm0; m1r = nm1;
        #pragma unroll
        for (int ni = 0; ni < 8; ni++) {
            o[ni][0] *= fac0; o[ni][1] *= fac0;
            o[ni][2] *= fac1; o[ni][3] *= fac1;
        }

        // ---- O += P @ V, row-sums via ones-column MMA ----
        float rsum[4] = {0.0f, 0.0f, 0.0f, 0.0f};
        #pragma unroll
        for (int kk = 0; kk < 8; kk++) {
            uint32_t afr[4] = { p01[2 * kk], p23[2 * kk],
                                p01[2 * kk + 1], p23[2 * kk + 1] };
            #pragma unroll
            for (int p = 0; p < 4; p++) {
                int d  = p * 16 + lnB;
                int ck = 2 * kk + lckB;
                uint32_t addr = vb_u +
                    (uint32_t)(((d << 6) + ((ck ^ (d & 7)) << 2)) << 2);
                uint32_t b0, b1, b2, b3;
                LDSM4(b0, b1, b2, b3, addr);
                uint32_t f0[2] = { b0, b1 };
                uint32_t f1[2] = { b2, b3 };
                MMA16(o[2 * p],     afr, f0);
                MMA16(o[2 * p + 1], afr, f1);
            }
            uint32_t of[2] = { ONES2, ONES2 };
            MMA16(rsum, afr, of);
        }

        l0r = l0r * fac0 + rsum[0];
        l1r = l1r * fac1 + rsum[2];

        if (kt < qt) {
            CP_WAIT(0);
            __syncthreads();
            buf ^= 1;
        }
    }

    // ---- normalize + write half ao ----
    float inv0 = 1.0f / l0r, inv1 = 1.0f / l1r;
    __half* aobase = aoh + (size_t)(b * SEQ + qt * 128) * HDIM + h * HS;
    #pragma unroll
    for (int ni = 0; ni < 8; ni++) {
        int c = ni * 8 + 2 * t;
        *(uint32_t*)(aobase + (size_t)(q0 + g) * HDIM + c) =
            f22h2(o[ni][0] * inv0, o[ni][1] * inv0);
        *(uint32_t*)(aobase + (size_t)(q0 + g + 8) * HDIM + c) =
            f22h2(o[ni][2] * inv1, o[ni][3] * inv1);
    }
}

// ---------------------------------------------------------------------------
extern "C" void kernel_launch(void* const* d_in, const int* in_sizes, int n_in,
                              void* d_out, int out_size)
{
    const float* x    = (const float*)d_in[0];
    const float* pos  = (const float*)d_in[1];
    const float* Wqkv = (const float*)d_in[2];
    const float* Wout = (const float*)d_in[3];
    float* out = (float*)d_out;

    __half *xh_p, *xph_p, *aoh_p, *qkh_p, *vT_p;
    uint32_t *wqkvT2_p, *woutT2_p;
    cudaGetSymbolAddress((void**)&xh_p,     g_xh);
    cudaGetSymbolAddress((void**)&xph_p,    g_xph);
    cudaGetSymbolAddress((void**)&aoh_p,    g_aoh);
    cudaGetSymbolAddress((void**)&qkh_p,    g_qkh);
    cudaGetSymbolAddress((void**)&vT_p,     g_vT);
    cudaGetSymbolAddress((void**)&wqkvT2_p, g_wqkvT2);
    cudaGetSymbolAddress((void**)&woutT2_p, g_woutT2);

    // 0) merged prep
    prep_all<<<MTOT + 3072 + 1024, 256>>>(x, pos, Wqkv, Wout,
                                          xh_p, xph_p, wqkvT2_p, woutT2_p);

    // 1) qkv projection (128x256 tiles, grid 384)
    {
        cudaFuncSetAttribute(gemm_h16<8>,
                             cudaFuncAttributeMaxDynamicSharedMemorySize, GemmCfg<8>::SMEM);
        dim3 grid(N_QKV / 256, MTOT / 128);
        gemm_h16<8><<<grid, 512, GemmCfg<8>::SMEM>>>(xph_p, xh_p, wqkvT2_p, nullptr,
                                                     qkh_p, vT_p, N_QKV, HDIM, 2048, 1);
    }

    // 2) flash attention (R13-exact)
    {
        cudaFuncSetAttribute(attn_h16,
                             cudaFuncAttributeMaxDynamicSharedMemorySize, ATTN_SMEM_BYTES);
        dim3 grid(SEQ / 128, 2 * NH);
        attn_h16<<<grid, 256, ATTN_SMEM_BYTES>>>(qkh_p, vT_p, aoh_p);
    }

    // 3) out = ao @ Wout (128x128 tiles, grid 256, 2 CTA/SM, full-chip wave)
    {
        cudaFuncSetAttribute(gemm_h16<4>,
                             cudaFuncAttributeMaxDynamicSharedMemorySize, GemmCfg<4>::SMEM);
        dim3 grid(HDIM / 128, MTOT / 128);
        gemm_h16<4><<<grid, 512, GemmCfg<4>::SMEM>>>(aoh_p, aoh_p, woutT2_p, out,
                                                     nullptr, nullptr, HDIM, HDIM, 0, 0);
    }
}

// round 16
// speedup vs baseline: 1.2042x; 1.1232x over previous
#include <cuda_runtime.h>
#include <cuda_fp16.h>
#include <math.h>
#include <stdint.h>

#define SEQ    2048
#define HDIM   1024
#define NH     16
#define HS     64
#define MTOT   4096            // B*S
#define N_QKV  3072            // 3*HDIM

// Scratch (allocation-free rule: device globals)
__device__ __half   g_xh   [(size_t)MTOT * HDIM];        // half(x)
__device__ __half   g_xph  [(size_t)MTOT * HDIM];        // half(x+pos)
__device__ __half   g_aoh  [(size_t)MTOT * HDIM];        // attention out, half
__device__ __half   g_qkh  [(size_t)MTOT * 2048];        // q|k half row-major (q pre-scaled)
__device__ __half   g_vT   [(size_t)HDIM * MTOT];        // v transposed
__device__ uint32_t g_wqkvT2[(size_t)N_QKV * (HDIM / 2)]; // W_qkv^T half2 (q cols pre-scaled)
__device__ uint32_t g_woutT2[(size_t)HDIM * (HDIM / 2)];  // W_out^T half2

// ---------------------------------------------------------------------------
// helpers
// ---------------------------------------------------------------------------
__device__ __forceinline__ uint32_t f22h2(float x, float y) {
    __half2 h = __floats2half2_rn(x, y);
    return *(uint32_t*)&h;
}
__device__ __forceinline__ float ex2(float x) {
    float r;
    asm("ex2.approx.ftz.f32 %0, %1;" : "=f"(r) : "f"(x));
    return r;
}
__device__ __forceinline__ uint32_t ex2h2(float a, float b) {
    uint32_t arg = f22h2(a, b), r;
    asm("ex2.approx.f16x2 %0, %1;" : "=r"(r) : "r"(arg));
    return r;
}
__device__ __forceinline__ uint32_t smem_u32(const void* p) {
    uint32_t a;
    asm("{ .reg .u64 t; cvta.to.shared.u64 t, %1; cvt.u32.u64 %0, t; }"
        : "=r"(a) : "l"(p));
    return a;
}

#define MMA16(d, a, b)                                                         \
    asm volatile(                                                              \
        "mma.sync.aligned.m16n8k16.row.col.f32.f16.f16.f32 "                   \
        "{%0,%1,%2,%3},{%4,%5,%6,%7},{%8,%9},{%0,%1,%2,%3};"                   \
        : "+f"((d)[0]), "+f"((d)[1]), "+f"((d)[2]), "+f"((d)[3])               \
        : "r"((a)[0]), "r"((a)[1]), "r"((a)[2]), "r"((a)[3]),                  \
          "r"((b)[0]), "r"((b)[1]))

#define LDSM4(r0, r1, r2, r3, addr)                                            \
    asm volatile("ldmatrix.sync.aligned.m8n8.x4.shared.b16 {%0,%1,%2,%3}, [%4];" \
        : "=r"(r0), "=r"(r1), "=r"(r2), "=r"(r3) : "r"(addr))

#define CP16(dst_u32, src_ptr)                                                 \
    asm volatile("cp.async.cg.shared.global [%0], [%1], 16;"                   \
        :: "r"(dst_u32), "l"(src_ptr))
#define CP_COMMIT() asm volatile("cp.async.commit_group;" ::: "memory")
#define CP_WAIT(n)  asm volatile("cp.async.wait_group %0;" :: "n"(n) : "memory")

// ---------------------------------------------------------------------------
// merged prep: x conversion + weight transposes (Q columns pre-scaled by 1/8)
// ---------------------------------------------------------------------------
__global__ __launch_bounds__(256)
void prep_all(const float* __restrict__ x, const float* __restrict__ pos,
              const float* __restrict__ Wqkv, const float* __restrict__ Wout,
              __half* __restrict__ xh, __half* __restrict__ xph,
              uint32_t* __restrict__ wqkvT2, uint32_t* __restrict__ woutT2)
{
    const int bid = blockIdx.x;
    const int tid = threadIdx.x;

    if (bid < MTOT) {
        const int m = bid;
        const int c = tid * 4;
        float4 xv = *(const float4*)(x + (size_t)m * HDIM + c);
        float4 pv = *(const float4*)(pos + (size_t)(m & (SEQ - 1)) * HDIM + c);
        uint2 u0; u0.x = f22h2(xv.x, xv.y); u0.y = f22h2(xv.z, xv.w);
        *(uint2*)(xh + (size_t)m * HDIM + c) = u0;
        uint2 u1; u1.x = f22h2(xv.x + pv.x, xv.y + pv.y);
        u1.y = f22h2(xv.z + pv.z, xv.w + pv.w);
        *(uint2*)(xph + (size_t)m * HDIM + c) = u1;
        return;
    }

    __shared__ float tile[32][33];
    const float* W;
    uint32_t* WT2;
    int bx, by, N;
    bool isqkv;
    if (bid < MTOT + 3072) {
        int id = bid - MTOT;
        W = Wqkv; WT2 = wqkvT2; N = N_QKV; isqkv = true;
        bx = id % (N_QKV / 32);
        by = id / (N_QKV / 32);
    } else {
        int id = bid - MTOT - 3072;
        W = Wout; WT2 = woutT2; N = HDIM; isqkv = false;
        bx = id % (HDIM / 32);
        by = id / (HDIM / 32);
    }
    const int K = HDIM;
    const int tx = tid & 31;
    const int ty = tid >> 5;
    #pragma unroll
    for (int i = ty; i < 32; i += 8)
        tile[i][tx] = W[(size_t)(by * 32 + i) * N + bx * 32 + tx];
    __syncthreads();
    // Q columns (n < 1024 of Wqkv) pre-scaled by exact 1/8 (softmax scale)
    const float scl = (isqkv && bx * 32 < 1024) ? 0.125f : 1.0f;
    #pragma unroll
    for (int it = 0; it < 2; it++) {
        int id = tid + it * 256;
        int nl = id >> 4;
        int kh = id & 15;
        WT2[(size_t)(bx * 32 + nl) * (K / 2) + by * 16 + kh] =
            f22h2(tile[2 * kh][nl] * scl, tile[2 * kh + 1][nl] * scl);
    }
}

// ---------------------------------------------------------------------------
// fp16 GEMM (R12/R13-exact): CTA tile 128x256, 512 thr, warp tile 32x64,
// K-step 64, 2-stage double buffer, ONE barrier per 64-k iteration.
// ---------------------------------------------------------------------------
#define GEMM_A_WORDS 4608
#define GEMM_B_WORDS 9216
#define GEMM_STG     (GEMM_A_WORDS + GEMM_B_WORDS)
#define GEMM_SMEM    (2 * GEMM_STG * 4)

__global__ __launch_bounds__(512, 1)
void gemm_h16(const __half* __restrict__ A0, const __half* __restrict__ A1,
              const uint32_t* __restrict__ BT2, float* __restrict__ Cf,
              __half* __restrict__ qkh, __half* __restrict__ vT,
              int N, int K, int ncut, int outmode)
{
    extern __shared__ uint32_t gsm[];
    const uint32_t s_u = smem_u32(gsm);

    const int tid  = threadIdx.x;
    const int lane = tid & 31;
    const int warp = tid >> 5;
    const int wm   = warp >> 2;
    const int wn   = warp & 3;
    const int g    = lane >> 2;
    const int t    = lane & 3;

    const int m0 = blockIdx.y * 128;
    const int n0 = blockIdx.x * 256;
    const __half* Aptr = (n0 < ncut) ? A0 : A1;

    const int lrow = lane & 15;
    const int lckA = lane >> 4;
    const int lnB  = (lane & 7) + 8 * ((lane >> 4) & 1);
    const int lckB = (lane >> 3) & 1;

    auto stage = [&](int tt, int bf) {
        const int k0 = tt << 6;
        const uint32_t abase = s_u + (uint32_t)(bf * GEMM_STG) * 4;
        const uint32_t bbase = abase + GEMM_A_WORDS * 4;
        #pragma unroll
        for (int it = 0; it < 2; it++) {
            int id  = tid + it * 512;
            int row = id >> 3;
            int ch  = id & 7;
            CP16(abase + (uint32_t)(row * 36 + ch * 4) * 4,
                 Aptr + (size_t)(m0 + row) * K + k0 + ch * 8);
        }
        #pragma unroll
        for (int it = 0; it < 4; it++) {
            int id = tid + it * 512;
            int n  = id >> 3;
            int ch = id & 7;
            CP16(bbase + (uint32_t)(n * 36 + ch * 4) * 4,
                 BT2 + (size_t)(n0 + n) * (K / 2) + (k0 >> 1) + ch * 4);
        }
    };

    float acc[2][8][4];
    #pragma unroll
    for (int i = 0; i < 2; i++)
        #pragma unroll
        for (int j = 0; j < 8; j++)
            #pragma unroll
            for (int c = 0; c < 4; c++)
                acc[i][j][c] = 0.0f;

    const int T = K >> 6;
    stage(0, 0); CP_COMMIT();

    for (int tt = 0; tt < T; tt++) {
        const int bf = tt & 1;
        CP_WAIT(0);
        __syncthreads();
        if (tt + 1 < T) {
            stage(tt + 1, bf ^ 1);
            CP_COMMIT();
        }

        const uint32_t ab = s_u + (uint32_t)(bf * GEMM_STG) * 4;
        const uint32_t bb = ab + GEMM_A_WORDS * 4;
        #pragma unroll
        for (int ks = 0; ks < 4; ks++) {
            uint32_t afr[2][4], bfr[8][2];
            #pragma unroll
            for (int mi = 0; mi < 2; mi++) {
                int row = wm * 32 + mi * 16 + lrow;
                LDSM4(afr[mi][0], afr[mi][1], afr[mi][2], afr[mi][3],
                      ab + (uint32_t)(row * 36 + (2 * ks + lckA) * 4) * 4);
            }
            #pragma unroll
            for (int p = 0; p < 4; p++) {
                int n = wn * 64 + p * 16 + lnB;
                LDSM4(bfr[2 * p][0], bfr[2 * p][1],
                      bfr[2 * p + 1][0], bfr[2 * p + 1][1],
                      bb + (uint32_t)(n * 36 + (2 * ks + lckB) * 4) * 4);
            }
            #pragma unroll
            for (int mi = 0; mi < 2; mi++)
                #pragma unroll
                for (int ni = 0; ni < 8; ni++)
                    MMA16(acc[mi][ni], afr[mi], bfr[ni]);
        }
    }

    // ---- epilogue ----
    if (outmode == 0) {
        #pragma unroll
        for (int mi = 0; mi < 2; mi++) {
            int row = m0 + wm * 32 + mi * 16 + g;
            #pragma unroll
            for (int ni = 0; ni < 8; ni++) {
                int col = n0 + wn * 64 + ni * 8 + 2 * t;
                *(float2*)(Cf + (size_t)row * N + col) =
                    make_float2(acc[mi][ni][0], acc[mi][ni][1]);
                *(float2*)(Cf + (size_t)(row + 8) * N + col) =
                    make_float2(acc[mi][ni][2], acc[mi][ni][3]);
            }
        }
    } else if (n0 < 2048) {
        #pragma unroll
        for (int mi = 0; mi < 2; mi++) {
            int row = m0 + wm * 32 + mi * 16 + g;
            #pragma unroll
            for (int ni = 0; ni < 8; ni++) {
                int col = n0 + wn * 64 + ni * 8 + 2 * t;
                *(uint32_t*)(qkh + (size_t)row * 2048 + col) =
                    f22h2(acc[mi][ni][0], acc[mi][ni][1]);
                *(uint32_t*)(qkh + (size_t)(row + 8) * 2048 + col) =
                    f22h2(acc[mi][ni][2], acc[mi][ni][3]);
            }
        }
    } else {
        #pragma unroll
        for (int mi = 0; mi < 2; mi++) {
            int row = m0 + wm * 32 + mi * 16 + g;
            #pragma unroll
            for (int ni = 0; ni < 8; ni++) {
                int colv = n0 - 2048 + wn * 64 + ni * 8 + 2 * t;
                vT[(size_t)colv * MTOT + row]           = __float2half_rn(acc[mi][ni][0]);
                vT[(size_t)(colv + 1) * MTOT + row]     = __float2half_rn(acc[mi][ni][1]);
                vT[(size_t)colv * MTOT + row + 8]       = __float2half_rn(acc[mi][ni][2]);
                vT[(size_t)(colv + 1) * MTOT + row + 8] = __float2half_rn(acc[mi][ni][3]);
            }
        }
    }
}

// ---------------------------------------------------------------------------
// Flash attention (causal) — R13 core. LPT grid: x = bh (32), y = q-tile,
// qt = gridDim.y-1-blockIdx.y so dispatch order is globally qt-descending
// (largest CTAs first; small ones pack the tail). Q pre-scaled in weights.
// ---------------------------------------------------------------------------
#define ATTN_SMEM_BYTES (4 * 4096 * 4)

__global__ __launch_bounds__(256, 2)
void attn_h16(const __half* __restrict__ qkh, const __half* __restrict__ vT,
              __half* __restrict__ aoh)
{
    extern __shared__ uint32_t usm[];
    const uint32_t usm_u = smem_u32(usm);

    const int tid  = threadIdx.x;
    const int lane = tid & 31;
    const int warp = tid >> 5;
    const int g    = lane >> 2;
    const int t    = lane & 3;
    const int q0   = warp * 16;
    const unsigned FULL = 0xffffffffu;

    const int lnB  = (lane & 7) + 8 * ((lane >> 4) & 1);
    const int lckB = (lane >> 3) & 1;

    const int bh = blockIdx.x;                              // 0..31
    const int b  = bh >> 4;
    const int h  = bh & 15;
    const int qt = (int)gridDim.y - 1 - (int)blockIdx.y;    // LPT: big first

    // ---- Q fragments in registers (already scaled via weights) ----
    uint32_t qf[4][4];
    {
        const __half* qb = qkh + (size_t)(b * SEQ + qt * 128 + q0 + g) * 2048 + h * HS;
        #pragma unroll
        for (int ks = 0; ks < 4; ks++) {
            qf[ks][0] = *(const uint32_t*)(qb + ks * 16 + 2 * t);
            qf[ks][1] = *(const uint32_t*)(qb + 8 * 2048 + ks * 16 + 2 * t);
            qf[ks][2] = *(const uint32_t*)(qb + ks * 16 + 2 * t + 8);
            qf[ks][3] = *(const uint32_t*)(qb + 8 * 2048 + ks * 16 + 2 * t + 8);
        }
    }

    const __half* kb0 = qkh + (size_t)(b * SEQ) * 2048 + 1024 + h * HS;
    const __half* vb0 = vT + (size_t)(h * HS) * MTOT + b * SEQ;

    auto stageKV = [&](int kt2, int bf) {
        const uint32_t kbase = usm_u + (uint32_t)(bf * 8192) * 4;
        const __half* kb = kb0 + (size_t)(kt2 * 128) * 2048;
        #pragma unroll
        for (int it = 0; it < 4; it++) {
            int id  = tid + it * 256;
            int key = id >> 3;
            int ch  = id & 7;
            CP16(kbase + (uint32_t)(((key << 5) + ((ch ^ (key & 7)) << 2)) << 2),
                 kb + (size_t)key * 2048 + ch * 8);
        }
        const __half* vb = vb0 + kt2 * 128;
        #pragma unroll
        for (int it = 0; it < 4; it++) {
            int id = tid + it * 256;
            int d  = id >> 4;
            int ch = id & 15;
            CP16(kbase + 4096 * 4 +
                     (uint32_t)((d * 64 + ((ch ^ (d & 7)) << 2)) << 2),
                 vb + (size_t)d * MTOT + ch * 8);
        }
    };

    float m0r = -1e30f, m1r = -1e30f, l0r = 0.0f, l1r = 0.0f;
    float o[8][4];
    #pragma unroll
    for (int ni = 0; ni < 8; ni++)
        o[ni][0] = o[ni][1] = o[ni][2] = o[ni][3] = 0.0f;

    const float L2E = 1.4426950408889634f;
    const uint32_t ONES2 = 0x3C003C00u;

    stageKV(0, 0); CP_COMMIT();
    CP_WAIT(0);
    __syncthreads();

    int buf = 0;
    for (int kt = 0; kt <= qt; kt++) {
        const uint32_t kb_u = usm_u + (uint32_t)(buf * 8192) * 4;
        const uint32_t vb_u = kb_u + 4096 * 4;

        // ---- S = Q @ K^T ----
        float sacc[16][4];
        #pragma unroll
        for (int ni = 0; ni < 16; ni++)
            sacc[ni][0] = sacc[ni][1] = sacc[ni][2] = sacc[ni][3] = 0.0f;

        #pragma unroll
        for (int ks = 0; ks < 4; ks++) {
            #pragma unroll
            for (int p = 0; p < 8; p++) {
                int key = p * 16 + lnB;
                int ck  = 2 * ks + lckB;
                uint32_t addr = kb_u +
                    (uint32_t)(((key << 5) + ((ck ^ (key & 7)) << 2)) << 2);
                uint32_t b0, b1, b2, b3;
                LDSM4(b0, b1, b2, b3, addr);
                uint32_t f0[2] = { b0, b1 };
                uint32_t f1[2] = { b2, b3 };
                MMA16(sacc[2 * p],     qf[ks], f0);
                MMA16(sacc[2 * p + 1], qf[ks], f1);
            }
        }

        // ---- causal mask (diagonal tile only) ----
        const int r0l = q0 + g, r1l = r0l + 8;
        if (kt == qt) {
            #pragma unroll
            for (int ni = 0; ni < 16; ni++) {
                int c = ni * 8 + 2 * t;
                if (c     > r0l) sacc[ni][0] = -1e30f;
                if (c + 1 > r0l) sacc[ni][1] = -1e30f;
                if (c     > r1l) sacc[ni][2] = -1e30f;
                if (c + 1 > r1l) sacc[ni][3] = -1e30f;
            }
        }

        // ---- stage next K/V tile EARLY ----
        if (kt < qt) {
            stageKV(kt + 1, buf ^ 1);
            CP_COMMIT();
        }

        // ---- row max (quad reduce) ----
        float rm0 = -1e30f, rm1 = -1e30f;
        #pragma unroll
        for (int ni = 0; ni < 16; ni++) {
            rm0 = fmaxf(rm0, fmaxf(sacc[ni][0], sacc[ni][1]));
            rm1 = fmaxf(rm1, fmaxf(sacc[ni][2], sacc[ni][3]));
        }
        rm0 = fmaxf(rm0, __shfl_xor_sync(FULL, rm0, 1));
        rm0 = fmaxf(rm0, __shfl_xor_sync(FULL, rm0, 2));
        rm1 = fmaxf(rm1, __shfl_xor_sync(FULL, rm1, 1));
        rm1 = fmaxf(rm1, __shfl_xor_sync(FULL, rm1, 2));

        float nm0 = fmaxf(m0r, rm0), nm1 = fmaxf(m1r, rm1);
        float fac0 = ex2((m0r - nm0) * L2E), fac1 = ex2((m1r - nm1) * L2E);
        float nb0 = nm0 * L2E, nb1 = nm1 * L2E;

        // ---- exp via f16x2 MUFU: result is the packed P fragment ----
        uint32_t p01[16], p23[16];
        #pragma unroll
        for (int ni = 0; ni < 16; ni++) {
            p01[ni] = ex2h2(fmaf(sacc[ni][0], L2E, -nb0),
                            fmaf(sacc[ni][1], L2E, -nb0));
            p23[ni] = ex2h2(fmaf(sacc[ni][2], L2E, -nb1),
                            fmaf(sacc[ni][3], L2E, -nb1));
        }

        m0r = nm0; m1r = nm1;
        #pragma unroll
        for (int ni = 0; ni < 8; ni++) {
            o[ni][0] *= fac0; o[ni][1] *= fac0;
            o[ni][2] *= fac1; o[ni][3] *= fac1;
        }

        // ---- O += P @ V, row-sums via ones-column MMA ----
        float rsum[4] = {0.0f, 0.0f, 0.0f, 0.0f};
        #pragma unroll
        for (int kk = 0; kk < 8; kk++) {
            uint32_t afr[4] = { p01[2 * kk], p23[2 * kk],
                                p01[2 * kk + 1], p23[2 * kk + 1] };
            #pragma unroll
            for (int p = 0; p < 4; p++) {
                int d  = p * 16 + lnB;
                int ck = 2 * kk + lckB;
                uint32_t addr = vb_u +
                    (uint32_t)(((d << 6) + ((ck ^ (d & 7)) << 2)) << 2);
                uint32_t b0, b1, b2, b3;
                LDSM4(b0, b1, b2, b3, addr);
                uint32_t f0[2] = { b0, b1 };
                uint32_t f1[2] = { b2, b3 };
                MMA16(o[2 * p],     afr, f0);
                MMA16(o[2 * p + 1], afr, f1);
            }
            uint32_t of[2] = { ONES2, ONES2 };
            MMA16(rsum, afr, of);
        }

        l0r = l0r * fac0 + rsum[0];
        l1r = l1r * fac1 + rsum[2];

        if (kt < qt) {
            CP_WAIT(0);
            __syncthreads();
            buf ^= 1;
        }
    }

    // ---- normalize + write half ao ----
    float inv0 = 1.0f / l0r, inv1 = 1.0f / l1r;
    __half* aobase = aoh + (size_t)(b * SEQ + qt * 128) * HDIM + h * HS;
    #pragma unroll
    for (int ni = 0; ni < 8; ni++) {
        int c = ni * 8 + 2 * t;
        *(uint32_t*)(aobase + (size_t)(q0 + g) * HDIM + c) =
            f22h2(o[ni][0] * inv0, o[ni][1] * inv0);
        *(uint32_t*)(aobase + (size_t)(q0 + g + 8) * HDIM + c) =
            f22h2(o[ni][2] * inv1, o[ni][3] * inv1);
    }
}

// ---------------------------------------------------------------------------
extern "C" void kernel_launch(void* const* d_in, const int* in_sizes, int n_in,
                              void* d_out, int out_size)
{
    const float* x    = (const float*)d_in[0];
    const float* pos  = (const float*)d_in[1];
    const float* Wqkv = (const float*)d_in[2];
    const float* Wout = (const float*)d_in[3];
    float* out = (float*)d_out;

    __half *xh_p, *xph_p, *aoh_p, *qkh_p, *vT_p;
    uint32_t *wqkvT2_p, *woutT2_p;
    cudaGetSymbolAddress((void**)&xh_p,     g_xh);
    cudaGetSymbolAddress((void**)&xph_p,    g_xph);
    cudaGetSymbolAddress((void**)&aoh_p,    g_aoh);
    cudaGetSymbolAddress((void**)&qkh_p,    g_qkh);
    cudaGetSymbolAddress((void**)&vT_p,     g_vT);
    cudaGetSymbolAddress((void**)&wqkvT2_p, g_wqkvT2);
    cudaGetSymbolAddress((void**)&woutT2_p, g_woutT2);

    // 0) merged prep (Q-scale folded into Wqkv transpose)
    prep_all<<<MTOT + 3072 + 1024, 256>>>(x, pos, Wqkv, Wout,
                                          xh_p, xph_p, wqkvT2_p, woutT2_p);

    // 1) qkv projection (128x256 tiles)
    {
        cudaFuncSetAttribute(gemm_h16,
                             cudaFuncAttributeMaxDynamicSharedMemorySize, GEMM_SMEM);
        dim3 grid(N_QKV / 256, MTOT / 128);
        gemm_h16<<<grid, 512, GEMM_SMEM>>>(xph_p, xh_p, wqkvT2_p, nullptr,
                                           qkh_p, vT_p, N_QKV, HDIM, 2048, 1);
    }

    // 2) flash attention (LPT dispatch: x=bh, y=qtile descending)
    {
        cudaFuncSetAttribute(attn_h16,
                             cudaFuncAttributeMaxDynamicSharedMemorySize, ATTN_SMEM_BYTES);
        dim3 grid(2 * NH, SEQ / 128);
        attn_h16<<<grid, 256, ATTN_SMEM_BYTES>>>(qkh_p, vT_p, aoh_p);
    }

    // 3) out = ao @ Wout (128x256 tiles, NFR=8 proven best)
    {
        dim3 grid(HDIM / 256, MTOT / 128);
        gemm_h16<<<grid, 512, GEMM_SMEM>>>(aoh_p, aoh_p, woutT2_p, out,
                                           nullptr, nullptr, HDIM, HDIM, 0, 0);
    }
}